// round 1
// baseline (speedup 1.0000x reference)
#include <cuda_runtime.h>
#include <math.h>

#define HEADS  24
#define HDIM   128
#define BATCH  2
#define TXT    256
#define IMG    1024
#define SEQ    1280          // TXT + IMG
#define DMODEL 3072
#define INNER  3072          // HEADS*HDIM
#define ROWS   (BATCH*SEQ)   // 2560

// ---------------- scratch (static device globals: allowed) ----------------
__device__ float g_x  [ROWS * DMODEL];            // concat input       30 MB
__device__ float g_qkv[ROWS * 3 * INNER];         // qkv gemm out       90 MB
__device__ float g_q  [BATCH * HEADS * SEQ * HDIM]; // 30 MB, [B,H,S,D]
__device__ float g_k  [BATCH * HEADS * SEQ * HDIM];
__device__ float g_v  [BATCH * HEADS * SEQ * HDIM];
__device__ float g_o  [ROWS * INNER];             // attn out [B,S,H*D] 30 MB

// ---------------- 1. concat ----------------
__global__ void concat_kernel(const float* __restrict__ hid,
                              const float* __restrict__ enc) {
    int idx = blockIdx.x * blockDim.x + threadIdx.x;     // float4 index
    const int total = ROWS * DMODEL / 4;
    if (idx >= total) return;
    int row  = idx / (DMODEL / 4);
    int col4 = idx % (DMODEL / 4);
    int b = row / SEQ, s = row % SEQ;
    const float4* src = (s < TXT)
        ? (const float4*)(enc + (size_t)(b * TXT + s) * DMODEL)
        : (const float4*)(hid + (size_t)(b * IMG + (s - TXT)) * DMODEL);
    ((float4*)g_x)[idx] = src[col4];
}

// ---------------- 2/5. SGEMM  C[M,N] = A[M,K] @ B[K,N] + bias ----------------
// BM=BN=128, BK=8, TM=TN=8, 256 threads. REMAP=1 reorders rows for final output.
template <int REMAP>
__global__ __launch_bounds__(256)
void sgemm_bias(int M, int N, int K,
                const float* __restrict__ A, const float* __restrict__ B,
                const float* __restrict__ bias, float* __restrict__ C) {
    const int BM = 128, BN = 128, BK = 8;
    __shared__ float As[BK][BM];   // transposed
    __shared__ float Bs[BK][BN];
    int tid = threadIdx.x;
    int br = blockIdx.y, bc = blockIdx.x;
    const float* Ab = A + (size_t)br * BM * K;
    const float* Bb = B + (size_t)bc * BN;
    int aRow = tid >> 1, aCol = (tid & 1) * 4;
    int bRow = tid >> 5, bCol = (tid & 31) * 4;
    int tr = (tid >> 4) * 8, tc = (tid & 15) * 8;
    float acc[8][8];
    #pragma unroll
    for (int i = 0; i < 8; i++)
        #pragma unroll
        for (int j = 0; j < 8; j++) acc[i][j] = 0.f;

    for (int k0 = 0; k0 < K; k0 += BK) {
        float4 a4 = *(const float4*)(Ab + (size_t)aRow * K + k0 + aCol);
        As[aCol + 0][aRow] = a4.x; As[aCol + 1][aRow] = a4.y;
        As[aCol + 2][aRow] = a4.z; As[aCol + 3][aRow] = a4.w;
        *(float4*)(&Bs[bRow][bCol]) =
            *(const float4*)(Bb + (size_t)(k0 + bRow) * N + bCol);
        __syncthreads();
        #pragma unroll
        for (int k = 0; k < BK; k++) {
            float rm[8], rn[8];
            *(float4*)(rm)     = *(const float4*)(&As[k][tr]);
            *(float4*)(rm + 4) = *(const float4*)(&As[k][tr + 4]);
            *(float4*)(rn)     = *(const float4*)(&Bs[k][tc]);
            *(float4*)(rn + 4) = *(const float4*)(&Bs[k][tc + 4]);
            #pragma unroll
            for (int i = 0; i < 8; i++)
                #pragma unroll
                for (int j = 0; j < 8; j++) acc[i][j] += rm[i] * rn[j];
        }
        __syncthreads();
    }
    #pragma unroll
    for (int i = 0; i < 8; i++) {
        int m = br * BM + tr + i;
        float* crow;
        if (REMAP) {
            int b = m / SEQ, s = m % SEQ;
            int orow = (s < TXT) ? (BATCH * IMG + b * TXT + s)
                                 : (b * IMG + (s - TXT));
            crow = C + (size_t)orow * N;
        } else {
            crow = C + (size_t)m * N;
        }
        #pragma unroll
        for (int j = 0; j < 8; j += 4) {
            int n = bc * 128 + tc + j;
            float4 v;
            v.x = acc[i][j + 0] + bias[n + 0];
            v.y = acc[i][j + 1] + bias[n + 1];
            v.z = acc[i][j + 2] + bias[n + 2];
            v.w = acc[i][j + 3] + bias[n + 3];
            *(float4*)(crow + n) = v;
        }
    }
}

// ---------------- 3. LayerNorm (no affine) + partial RoPE ----------------
// one warp per (b,s,h); handles q,k (LN [+RoPE]) and v (copy).
__global__ void ln_rope_kernel(const float* __restrict__ cosb,
                               const float* __restrict__ sinb) {
    int gw   = (blockIdx.x * blockDim.x + threadIdx.x) >> 5;
    int lane = threadIdx.x & 31;
    if (gw >= BATCH * SEQ * HEADS) return;
    int h = gw % HEADS;
    int s = (gw / HEADS) % SEQ;
    int b = gw / (HEADS * SEQ);
    const float* base = g_qkv + (size_t)(b * SEQ + s) * (3 * INNER) + h * HDIM;
    size_t orow = ((size_t)(b * HEADS + h) * SEQ + s) * HDIM;
    bool img = (s >= TXT);
    float c4[4], s4[4];
    if (img) {
        float4 cv = *(const float4*)(cosb + (size_t)(s - TXT) * HDIM + lane * 4);
        float4 sv = *(const float4*)(sinb + (size_t)(s - TXT) * HDIM + lane * 4);
        c4[0] = cv.x; c4[1] = cv.y; c4[2] = cv.z; c4[3] = cv.w;
        s4[0] = sv.x; s4[1] = sv.y; s4[2] = sv.z; s4[3] = sv.w;
    }
    float sgn = (lane < 16) ? -1.f : 1.f;  // lower half: -imag, upper: +real
    #pragma unroll
    for (int qk = 0; qk < 2; qk++) {
        float4 xv = *(const float4*)(base + qk * INNER + lane * 4);
        float x[4] = {xv.x, xv.y, xv.z, xv.w};
        float sum = x[0] + x[1] + x[2] + x[3];
        #pragma unroll
        for (int o = 16; o > 0; o >>= 1) sum += __shfl_xor_sync(0xffffffffu, sum, o);
        float mu = sum * (1.f / 128.f);
        float vs = 0.f;
        #pragma unroll
        for (int i = 0; i < 4; i++) { float d = x[i] - mu; vs += d * d; x[i] = d; }
        #pragma unroll
        for (int o = 16; o > 0; o >>= 1) vs += __shfl_xor_sync(0xffffffffu, vs, o);
        float inv = rsqrtf(vs * (1.f / 128.f) + 1e-5f);
        #pragma unroll
        for (int i = 0; i < 4; i++) x[i] *= inv;
        if (img) {
            float p[4];
            #pragma unroll
            for (int i = 0; i < 4; i++) p[i] = __shfl_xor_sync(0xffffffffu, x[i], 16);
            #pragma unroll
            for (int i = 0; i < 4; i++) x[i] = x[i] * c4[i] + sgn * p[i] * s4[i];
        }
        float4 ov = {x[0], x[1], x[2], x[3]};
        float* dst = qk == 0 ? g_q : g_k;
        *(float4*)(dst + orow + lane * 4) = ov;
    }
    *(float4*)(g_v + orow + lane * 4) = *(const float4*)(base + 2 * INNER + lane * 4);
}

// ---------------- 4. flash attention (fp32, online softmax) ----------------
// Br=Bc=64, D=128, 256 threads (16x16). grid (20, 24, 2).
#define QPAD 129
#define PPAD 65
__global__ __launch_bounds__(256)
void attn_kernel() {
    extern __shared__ float sm[];
    float* Qs   = sm;                   // 64*129
    float* Ks   = Qs + 64 * QPAD;       // 64*129
    float* Vs   = Ks + 64 * QPAD;       // 64*128
    float* Ps   = Vs + 64 * HDIM;       // 64*65
    float* rowm = Ps + 64 * PPAD;
    float* rowl = rowm + 64;
    float* rowf = rowl + 64;

    int qt = blockIdx.x, h = blockIdx.y, b = blockIdx.z;
    int tid = threadIdx.x;
    int ty = tid >> 4, tx = tid & 15;
    size_t hb = (size_t)(b * HEADS + h) * SEQ * HDIM;
    const float* qb = g_q + hb;
    const float* kb = g_k + hb;
    const float* vb = g_v + hb;

    for (int i = tid; i < 64 * 32; i += 256) {          // 2048 float4
        int r = i >> 5, c4 = i & 31;
        float4 v = *(const float4*)(qb + (size_t)(qt * 64 + r) * HDIM + c4 * 4);
        Qs[r * QPAD + c4 * 4 + 0] = v.x; Qs[r * QPAD + c4 * 4 + 1] = v.y;
        Qs[r * QPAD + c4 * 4 + 2] = v.z; Qs[r * QPAD + c4 * 4 + 3] = v.w;
    }
    if (tid < 64) { rowm[tid] = -INFINITY; rowl[tid] = 0.f; }

    float acc[4][8];
    #pragma unroll
    for (int i = 0; i < 4; i++)
        #pragma unroll
        for (int c = 0; c < 8; c++) acc[i][c] = 0.f;

    const float scale = 0.08838834764831845f;           // 1/sqrt(128)

    for (int kt = 0; kt < SEQ / 64; kt++) {
        for (int i = tid; i < 64 * 32; i += 256) {
            int r = i >> 5, c4 = i & 31;
            float4 kv = *(const float4*)(kb + (size_t)(kt * 64 + r) * HDIM + c4 * 4);
            Ks[r * QPAD + c4 * 4 + 0] = kv.x; Ks[r * QPAD + c4 * 4 + 1] = kv.y;
            Ks[r * QPAD + c4 * 4 + 2] = kv.z; Ks[r * QPAD + c4 * 4 + 3] = kv.w;
            *(float4*)(Vs + r * HDIM + c4 * 4) =
                *(const float4*)(vb + (size_t)(kt * 64 + r) * HDIM + c4 * 4);
        }
        __syncthreads();

        // S = Q @ K^T  (rows ty+16*ii, cols tx+16*jj)
        float sacc[4][4];
        #pragma unroll
        for (int i = 0; i < 4; i++)
            #pragma unroll
            for (int j = 0; j < 4; j++) sacc[i][j] = 0.f;
        #pragma unroll 4
        for (int d = 0; d < HDIM; d++) {
            float qr[4], kr[4];
            #pragma unroll
            for (int ii = 0; ii < 4; ii++) qr[ii] = Qs[(ty + 16 * ii) * QPAD + d];
            #pragma unroll
            for (int jj = 0; jj < 4; jj++) kr[jj] = Ks[(tx + 16 * jj) * QPAD + d];
            #pragma unroll
            for (int ii = 0; ii < 4; ii++)
                #pragma unroll
                for (int jj = 0; jj < 4; jj++) sacc[ii][jj] += qr[ii] * kr[jj];
        }
        #pragma unroll
        for (int ii = 0; ii < 4; ii++)
            #pragma unroll
            for (int jj = 0; jj < 4; jj++)
                Ps[(ty + 16 * ii) * PPAD + tx + 16 * jj] = sacc[ii][jj] * scale;
        __syncthreads();

        // online softmax (one thread per row)
        if (tid < 64) {
            float m_old = rowm[tid];
            float mx = m_old;
            float* pr = Ps + tid * PPAD;
            #pragma unroll 8
            for (int j = 0; j < 64; j++) mx = fmaxf(mx, pr[j]);
            float f = __expf(m_old - mx);
            float sum = 0.f;
            #pragma unroll 8
            for (int j = 0; j < 64; j++) {
                float p = __expf(pr[j] - mx);
                pr[j] = p; sum += p;
            }
            rowl[tid] = rowl[tid] * f + sum;
            rowm[tid] = mx;
            rowf[tid] = f;
        }
        __syncthreads();

        // rescale + O += P @ V  (cols tx+16*cc)
        #pragma unroll
        for (int ii = 0; ii < 4; ii++) {
            float f = rowf[ty + 16 * ii];
            #pragma unroll
            for (int cc = 0; cc < 8; cc++) acc[ii][cc] *= f;
        }
        #pragma unroll 4
        for (int j = 0; j < 64; j++) {
            float pv[4], vv[8];
            #pragma unroll
            for (int ii = 0; ii < 4; ii++) pv[ii] = Ps[(ty + 16 * ii) * PPAD + j];
            #pragma unroll
            for (int cc = 0; cc < 8; cc++) vv[cc] = Vs[j * HDIM + tx + 16 * cc];
            #pragma unroll
            for (int ii = 0; ii < 4; ii++)
                #pragma unroll
                for (int cc = 0; cc < 8; cc++) acc[ii][cc] += pv[ii] * vv[cc];
        }
        __syncthreads();
    }

    // write O as [B, S, H*D]
    float* ob = g_o + ((size_t)b * SEQ + qt * 64) * INNER + h * HDIM;
    #pragma unroll
    for (int ii = 0; ii < 4; ii++) {
        int r = ty + 16 * ii;
        float inv = 1.f / rowl[r];
        #pragma unroll
        for (int cc = 0; cc < 8; cc++)
            ob[(size_t)r * INNER + tx + 16 * cc] = acc[ii][cc] * inv;
    }
}

// ---------------- host ----------------
extern "C" void kernel_launch(void* const* d_in, const int* in_sizes, int n_in,
                              void* d_out, int out_size) {
    const float* hid   = (const float*)d_in[0];
    const float* enc   = (const float*)d_in[1];
    const float* cosb  = (const float*)d_in[2];
    const float* sinb  = (const float*)d_in[3];
    const float* w_qkv = (const float*)d_in[4];
    const float* b_qkv = (const float*)d_in[5];
    const float* w_out = (const float*)d_in[6];
    const float* b_out = (const float*)d_in[7];
    float* out = (float*)d_out;

    float *xp, *qkvp, *op;
    cudaGetSymbolAddress((void**)&xp,   g_x);
    cudaGetSymbolAddress((void**)&qkvp, g_qkv);
    cudaGetSymbolAddress((void**)&op,   g_o);

    // 1. concat
    {
        int total = ROWS * DMODEL / 4;
        concat_kernel<<<(total + 255) / 256, 256>>>(hid, enc);
    }
    // 2. qkv gemm: [2560,3072] @ [3072,9216]
    {
        dim3 grid(3 * INNER / 128, ROWS / 128);
        sgemm_bias<0><<<grid, 256>>>(ROWS, 3 * INNER, DMODEL, xp, w_qkv, b_qkv, qkvp);
    }
    // 3. LN + RoPE
    {
        int warps = BATCH * SEQ * HEADS;
        ln_rope_kernel<<<(warps + 7) / 8, 256>>>(cosb, sinb);
    }
    // 4. attention
    {
        size_t smem = (size_t)(64 * QPAD * 2 + 64 * HDIM + 64 * PPAD + 192) * sizeof(float);
        cudaFuncSetAttribute(attn_kernel, cudaFuncAttributeMaxDynamicSharedMemorySize,
                             (int)smem);
        dim3 grid(SEQ / 64, HEADS, BATCH);
        attn_kernel<<<grid, 256, smem>>>();
    }
    // 5. out proj with row remap: [2560,3072] @ [3072,3072]
    {
        dim3 grid(DMODEL / 128, ROWS / 128);
        sgemm_bias<1><<<grid, 256>>>(ROWS, DMODEL, DMODEL, op, w_out, b_out, out);
    }
}